// round 15
// baseline (speedup 1.0000x reference)
#include <cuda_runtime.h>
#include <cuda_fp16.h>
#include <cstdint>

// ============================================================================
// Shapes: y = x[8192,4096] @ sign(W)[4096,4096]^T ; BN over batch; sign
// 2-plane fp16 split: x = hi + mid, residual <= 2^-23 |x| (negligible).
// R15 = single fused GEMM pass (both planes, dual accumulators, 512 thr,
//       warp tile 32x32, 2-stage) + stats fold + wide stats2.
// Accumulation order per element identical to the split version.
// ============================================================================
#define BATCH   8192
#define DIN     4096
#define DOUT    4096

// CTA 128(M) x 128(N), 16 warps 4(M)x4(N), warp tile 32x32, K chunk 64
#define TM      128
#define TN      128
#define TK      64
#define KROWB   128
#define NCHUNK  (DIN / TK)                     // 64
#define NTHREAD 512

#define TILE16K       (TM * KROWB)             // 16384 (one 128x64 fp16 tile)
#define STAGE_BYTES   (3 * TILE16K)            // 48KB: A_hi + A_mid + B
#define NSTAGE        2
#define GEMM_SMEM     (NSTAGE * STAGE_BYTES)   // 98304 -> 2 CTAs/SM

#define NSEG    64                              // = gridDim.y of GEMM

// ============================================================================
// Scratch (device globals — allocation-free rule)
// ============================================================================
__device__ __half g_Wb [(size_t)DOUT * DIN];
__device__ __half g_Ahi[(size_t)BATCH * DIN];
__device__ __half g_Amd[(size_t)BATCH * DIN];
__device__ float  g_y  [(size_t)BATCH * DOUT];
__device__ float  g_psum  [NSEG * DOUT];
__device__ float  g_psumsq[NSEG * DOUT];
__device__ float  g_mean[DOUT];
__device__ float  g_rstd[DOUT];

// ============================================================================
// Helpers (baseline-PTX only: cp.async / ldmatrix / mma.sync)
// ============================================================================
__device__ __forceinline__ uint32_t smem_u32(const void* p) {
    uint32_t a;
    asm("{ .reg .u64 t; cvta.to.shared.u64 t, %1; cvt.u32.u64 %0, t; }"
        : "=r"(a) : "l"(p));
    return a;
}

__device__ __forceinline__ void cp_async16(uint32_t dst, const void* src) {
    asm volatile("cp.async.cg.shared.global [%0], [%1], 16;\n"
                 :: "r"(dst), "l"(src) : "memory");
}
__device__ __forceinline__ void cp_commit() {
    asm volatile("cp.async.commit_group;\n" ::: "memory");
}
template <int N>
__device__ __forceinline__ void cp_wait() {
    asm volatile("cp.async.wait_group %0;\n" :: "n"(N) : "memory");
}

__device__ __forceinline__ void ldmx4(uint32_t* r, uint32_t addr) {
    asm volatile("ldmatrix.sync.aligned.m8n8.x4.shared.b16 {%0,%1,%2,%3}, [%4];"
                 : "=r"(r[0]), "=r"(r[1]), "=r"(r[2]), "=r"(r[3]) : "r"(addr));
}

// fp16 inputs, fp32 accumulate
__device__ __forceinline__ void mma16816(float* d, const uint32_t* a,
                                         uint32_t b0, uint32_t b1) {
    asm volatile(
        "mma.sync.aligned.m16n8k16.row.col.f32.f16.f16.f32 "
        "{%0,%1,%2,%3}, {%4,%5,%6,%7}, {%8,%9}, {%0,%1,%2,%3};"
        : "+f"(d[0]), "+f"(d[1]), "+f"(d[2]), "+f"(d[3])
        : "r"(a[0]), "r"(a[1]), "r"(a[2]), "r"(a[3]), "r"(b0), "r"(b1));
}

__device__ __forceinline__ uint32_t sw128(uint32_t off) {
    return off ^ ((off >> 3) & 0x70);
}

// ============================================================================
// Prep (merged): binarize W -> fp16 AND split x into 2 fp16 planes
// ============================================================================
#define NW4   (DOUT * DIN / 4)
#define NX4   (BATCH * DIN / 4)

__global__ void prep_kernel(const float* __restrict__ W,
                            const float* __restrict__ x) {
    size_t gi = (size_t)blockIdx.x * blockDim.x + threadIdx.x;
    if (gi < (size_t)NW4) {
        float4 v = ((const float4*)W)[gi];
        float vv[4] = {v.x, v.y, v.z, v.w};
        __half s[4];
#pragma unroll
        for (int j = 0; j < 4; ++j)
            s[j] = __float2half(vv[j] > 0.f ? 1.f : (vv[j] < 0.f ? -1.f : 0.f));
        ((uint2*)g_Wb)[gi] = *(uint2*)s;
    } else {
        size_t i = gi - NW4;
        if (i >= (size_t)NX4) return;
        float4 v = ((const float4*)x)[i];
        float vv[4] = {v.x, v.y, v.z, v.w};
        __half hi[4], md[4];
#pragma unroll
        for (int j = 0; j < 4; ++j) {
            float f = vv[j];
            __half h = __float2half_rn(f);
            float r1 = f - __half2float(h);
            __half m = __float2half_rn(r1);
            hi[j] = h; md[j] = m;
        }
        ((uint2*)g_Ahi)[i] = *(uint2*)hi;
        ((uint2*)g_Amd)[i] = *(uint2*)md;
    }
}

// ============================================================================
// Fused GEMM: acc_hi = hi.Wb^T (K-sequential), acc_mid = mid.Wb^T,
//   y = (acc_hi + acc_mid) + bias  (same rounding order as split version),
//   plus per-tile column stats into g_psum/g_psumsq (replaces stats1).
//   512 threads, 16 warps 4(M)x4(N), warp tile 32x32, 2 CTAs/SM, 2-stage.
//   Mainloop schedule = R10 structure: wait; sync; compute; sync; fill(kc+2).
// ============================================================================
__global__ void __launch_bounds__(NTHREAD, 2)
gemm_fused_kernel(const float* __restrict__ bias) {
    extern __shared__ __align__(1024) char smem[];
    const uint32_t sbase = smem_u32(smem);
    const int tid  = threadIdx.x;
    const int wid  = tid >> 5;
    const int lane = tid & 31;
    const int o0 = blockIdx.x * TN;
    const int m0 = blockIdx.y * TM;

    float acc_hi[2][4][4];
    float acc_md[2][4][4];
#pragma unroll
    for (int a = 0; a < 2; ++a)
#pragma unroll
        for (int b = 0; b < 4; ++b)
#pragma unroll
            for (int c = 0; c < 4; ++c) { acc_hi[a][b][c] = 0.f; acc_md[a][b][c] = 0.f; }

    // stage fill: 3072 x 16B (A_hi 1024, A_mid 1024, B 1024)
    auto fill = [&](int s, int kc) {
        const int kcol = kc * TK;
        const uint32_t stage = sbase + s * STAGE_BYTES;
#pragma unroll
        for (int iter = 0; iter < 6; ++iter) {
            int t = tid + iter * NTHREAD;
            int u = t & 1023;
            int row = u >> 3, c16 = u & 7;
            uint32_t loff = sw128((uint32_t)(row * KROWB + c16 * 16));
            if (t < 1024) {
                const void* src = g_Ahi + (size_t)(m0 + row) * DIN + kcol + c16 * 8;
                cp_async16(stage + loff, src);
            } else if (t < 2048) {
                const void* src = g_Amd + (size_t)(m0 + row) * DIN + kcol + c16 * 8;
                cp_async16(stage + TILE16K + loff, src);
            } else {
                const void* src = g_Wb + (size_t)(o0 + row) * DIN + kcol + c16 * 8;
                cp_async16(stage + 2 * TILE16K + loff, src);
            }
        }
        cp_commit();
    };

    const int lrow = lane & 15;
    const int lkh  = (lane >> 4) * 16;
    const int wm = (wid & 3) * 32;              // warp M offset (4 tiles)
    const int wn = (wid >> 2) * 32;             // warp N offset (4 tiles)
    uint32_t arow[2], brow[2];
#pragma unroll
    for (int mi = 0; mi < 2; ++mi) arow[mi] = (uint32_t)((wm + mi * 16 + lrow) * KROWB);
#pragma unroll
    for (int nt = 0; nt < 2; ++nt) brow[nt] = (uint32_t)((wn + nt * 16 + lrow) * KROWB);

    fill(0, 0); fill(1, 1);

    for (int kc = 0; kc < NCHUNK; ++kc) {
        if (kc < NCHUNK - 1) cp_wait<1>();
        else                 cp_wait<0>();
        __syncthreads();

        const uint32_t stage = sbase + (kc & 1) * STAGE_BYTES;
        const uint32_t Bb = stage + 2 * TILE16K;
#pragma unroll
        for (int ks = 0; ks < 4; ++ks) {
            const uint32_t kb = (uint32_t)(ks * 32 + lkh);
            uint32_t bf[2][4];
#pragma unroll
            for (int nt = 0; nt < 2; ++nt) ldmx4(bf[nt], Bb + sw128(brow[nt] + kb));
            // plane 0: hi -> acc_hi (isolated, K-sequential)
            {
                uint32_t af[2][4];
#pragma unroll
                for (int mi = 0; mi < 2; ++mi) ldmx4(af[mi], stage + sw128(arow[mi] + kb));
#pragma unroll
                for (int mi = 0; mi < 2; ++mi) {
#pragma unroll
                    for (int ni = 0; ni < 4; ++ni) {
                        const int nt = ni >> 1, sel = ni & 1;
                        mma16816(acc_hi[mi][ni], af[mi], bf[nt][sel], bf[nt][sel + 2]);
                    }
                }
            }
            // plane 1: mid -> acc_md
            {
                uint32_t af[2][4];
#pragma unroll
                for (int mi = 0; mi < 2; ++mi)
                    ldmx4(af[mi], stage + TILE16K + sw128(arow[mi] + kb));
#pragma unroll
                for (int mi = 0; mi < 2; ++mi) {
#pragma unroll
                    for (int ni = 0; ni < 4; ++ni) {
                        const int nt = ni >> 1, sel = ni & 1;
                        mma16816(acc_md[mi][ni], af[mi], bf[nt][sel], bf[nt][sel + 2]);
                    }
                }
            }
        }
        __syncthreads();
        if (kc + NSTAGE < NCHUNK) fill(kc & 1, kc + NSTAGE);
    }

    // ---- epilogue: y = (hi + mid) + bias; per-tile column stats ----
    const int r0 = lane >> 2;
    const int c0 = (lane & 3) * 2;

    float csum[4][2], csq[4][2];
#pragma unroll
    for (int ni = 0; ni < 4; ++ni) {
        csum[ni][0] = csum[ni][1] = 0.f;
        csq[ni][0] = csq[ni][1] = 0.f;
    }

#pragma unroll
    for (int mi = 0; mi < 2; ++mi) {
        const int row = m0 + wm + mi * 16 + r0;
        float* yr = g_y + (size_t)row * DOUT;
#pragma unroll
        for (int ni = 0; ni < 4; ++ni) {
            const int col = o0 + wn + ni * 8 + c0;
            const float bx = bias[col], by = bias[col + 1];
            float v00 = (acc_hi[mi][ni][0] + acc_md[mi][ni][0]) + bx;
            float v01 = (acc_hi[mi][ni][1] + acc_md[mi][ni][1]) + by;
            float v10 = (acc_hi[mi][ni][2] + acc_md[mi][ni][2]) + bx;
            float v11 = (acc_hi[mi][ni][3] + acc_md[mi][ni][3]) + by;
            float2 w0 = {v00, v01};
            float2 w1 = {v10, v11};
            *(float2*)(yr + col) = w0;
            *(float2*)(yr + (size_t)8 * DOUT + col) = w1;
            csum[ni][0] += v00 + v10;  csum[ni][1] += v01 + v11;
            csq[ni][0]  += v00 * v00 + v10 * v10;
            csq[ni][1]  += v01 * v01 + v11 * v11;
        }
    }

    // mainloop's last iteration ended with trailing __syncthreads(), but the
    // epilogue above has no barrier yet; sync before reusing stage smem.
    __syncthreads();

    // smem reduction: 32 partial slots x 128 cols (slot = (wid&3)*8 + r0)
    float* ssum = (float*)smem;            // 4096 floats (16KB)
    float* ssq  = ssum + 32 * TN;          // 4096 floats (16KB)
    const int slot = (wid & 3) * 8 + r0;   // 0..31
#pragma unroll
    for (int ni = 0; ni < 4; ++ni) {
#pragma unroll
        for (int j = 0; j < 2; ++j) {
            const int lc = wn + ni * 8 + c0 + j;   // 0..127 local col
            ssum[slot * TN + lc] = csum[ni][j];
            ssq [slot * TN + lc] = csq[ni][j];
        }
    }
    __syncthreads();

    if (tid < TN) {
        float s = 0.f;
#pragma unroll
        for (int g = 0; g < 32; ++g) s += ssum[g * TN + tid];
        g_psum[blockIdx.y * DOUT + o0 + tid] = s;
    } else if (tid < 2 * TN) {
        const int lc = tid - TN;
        float q = 0.f;
#pragma unroll
        for (int g = 0; g < 32; ++g) q += ssq[g * TN + lc];
        g_psumsq[blockIdx.y * DOUT + o0 + lc] = q;
    }
}

// ============================================================================
// Kernel 5: finalize mean / rstd — 8 threads/column, 128 blocks (all SMs)
// ============================================================================
__global__ void stats2_kernel() {
    __shared__ double sh_s[8][32];
    __shared__ double sh_q[8][32];
    const int lc   = threadIdx.x & 31;
    const int part = threadIdx.x >> 5;
    const int col  = blockIdx.x * 32 + lc;

    double s = 0.0, q = 0.0;
#pragma unroll
    for (int g = 0; g < 8; ++g) {
        const int seg = part * 8 + g;
        s += (double)g_psum[seg * DOUT + col];
        q += (double)g_psumsq[seg * DOUT + col];
    }
    sh_s[part][lc] = s;
    sh_q[part][lc] = q;
    __syncthreads();

    if (part == 0) {
        double st = ((sh_s[0][lc] + sh_s[1][lc]) + (sh_s[2][lc] + sh_s[3][lc]))
                  + ((sh_s[4][lc] + sh_s[5][lc]) + (sh_s[6][lc] + sh_s[7][lc]));
        double qt = ((sh_q[0][lc] + sh_q[1][lc]) + (sh_q[2][lc] + sh_q[3][lc]))
                  + ((sh_q[4][lc] + sh_q[5][lc]) + (sh_q[6][lc] + sh_q[7][lc]));
        const double inv_n = 1.0 / (double)BATCH;
        double mean = st * inv_n;
        double var = qt * inv_n - mean * mean;
        if (var < 0.0) var = 0.0;
        g_mean[col] = (float)mean;
        g_rstd[col] = (float)(1.0 / sqrt(var + 1e-5));
    }
}

// ============================================================================
// Kernel 6: normalize + sign -> out   (4 elems/thread — proven form)
// ============================================================================
__global__ void sign_kernel(const float* __restrict__ gamma,
                            const float* __restrict__ beta,
                            float* __restrict__ out) {
    size_t i = (size_t)blockIdx.x * blockDim.x + threadIdx.x;
    const size_t n4 = (size_t)BATCH * DOUT / 4;
    if (i >= n4) return;
    const int o = (int)((i * 4) & (DOUT - 1));
    float4 y = ((const float4*)g_y)[i];
    float yy[4] = {y.x, y.y, y.z, y.w};
    float4 r;
    float* rr = &r.x;
#pragma unroll
    for (int j = 0; j < 4; ++j) {
        float v = (yy[j] - g_mean[o + j]) * g_rstd[o + j] * gamma[o + j] + beta[o + j];
        rr[j] = (v > 0.f) ? 1.f : ((v < 0.f) ? -1.f : 0.f);
    }
    ((float4*)out)[i] = r;
}

// ============================================================================
// Launcher
// ============================================================================
extern "C" void kernel_launch(void* const* d_in, const int* in_sizes, int n_in,
                              void* d_out, int out_size) {
    const float* x     = (const float*)d_in[0];
    const float* W     = (const float*)d_in[1];
    const float* b     = (const float*)d_in[2];
    const float* gamma = (const float*)d_in[3];
    const float* beta  = (const float*)d_in[4];
    float* out = (float*)d_out;

    cudaFuncSetAttribute(gemm_fused_kernel,
                         cudaFuncAttributeMaxDynamicSharedMemorySize, GEMM_SMEM);

    {   // merged prep: binarize W -> fp16, split x into hi/mid fp16 planes
        const long long total = (long long)NW4 + NX4;
        prep_kernel<<<(int)((total + 255) / 256), 256>>>(W, x);
    }
    {   // fused GEMM (both planes + bias + column stats partials)
        dim3 grid(DOUT / TN, BATCH / TM);   // (32, 64)
        gemm_fused_kernel<<<grid, NTHREAD, GEMM_SMEM>>>(b);
    }
    {   // finalize stats, then normalize + sign
        stats2_kernel<<<DOUT / 32, 256>>>();
        const int n4 = BATCH * DOUT / 4;
        sign_kernel<<<(n4 + 255) / 256, 256>>>(gamma, beta, out);
    }
}

// round 16
// speedup vs baseline: 3.5082x; 3.5082x over previous
#include <cuda_runtime.h>
#include <cuda_fp16.h>
#include <cstdint>

// ============================================================================
// Shapes: y = x[8192,4096] @ sign(W)[4096,4096]^T ; BN over batch; sign
// 2-plane fp16 split: x = hi + mid, residual <= 2^-23 |x| (negligible).
// R16 = R14 exactly (session best: 1529.9us). R15's fused variant spilled
// registers (5367us) and is abandoned.
// ============================================================================
#define BATCH   8192
#define DIN     4096
#define DOUT    4096

// CTA 128(M) x 128(N), 8 warps 2(M)x4(N), warp tile 64x32, K chunk 64
#define TM      128
#define TN      128
#define TK      64
#define KROWB   128
#define NCHUNK  (DIN / TK)                     // 64

#define TILE16K       (TM * KROWB)             // 16384 (one 128x64 fp16 tile)
#define STAGE_BYTES   (2 * TILE16K)            // 32KB: A + B
#define NSTAGE        3
#define GEMM_SMEM     (NSTAGE * STAGE_BYTES)   // 98304 -> 2 CTAs/SM

#define NSEG    64                              // = gridDim.y of GEMM

// ============================================================================
// Scratch (device globals — allocation-free rule)
// ============================================================================
__device__ __half g_Wb [(size_t)DOUT * DIN];
__device__ __half g_Ahi[(size_t)BATCH * DIN];
__device__ __half g_Amd[(size_t)BATCH * DIN];
__device__ float  g_y  [(size_t)BATCH * DOUT];
__device__ float  g_psum  [NSEG * DOUT];
__device__ float  g_psumsq[NSEG * DOUT];
__device__ float  g_mean[DOUT];
__device__ float  g_rstd[DOUT];

// ============================================================================
// Helpers (baseline-PTX only: cp.async / ldmatrix / mma.sync)
// ============================================================================
__device__ __forceinline__ uint32_t smem_u32(const void* p) {
    uint32_t a;
    asm("{ .reg .u64 t; cvta.to.shared.u64 t, %1; cvt.u32.u64 %0, t; }"
        : "=r"(a) : "l"(p));
    return a;
}

__device__ __forceinline__ void cp_async16(uint32_t dst, const void* src) {
    asm volatile("cp.async.cg.shared.global [%0], [%1], 16;\n"
                 :: "r"(dst), "l"(src) : "memory");
}
__device__ __forceinline__ void cp_commit() {
    asm volatile("cp.async.commit_group;\n" ::: "memory");
}
template <int N>
__device__ __forceinline__ void cp_wait() {
    asm volatile("cp.async.wait_group %0;\n" :: "n"(N) : "memory");
}

__device__ __forceinline__ void ldmx4(uint32_t* r, uint32_t addr) {
    asm volatile("ldmatrix.sync.aligned.m8n8.x4.shared.b16 {%0,%1,%2,%3}, [%4];"
                 : "=r"(r[0]), "=r"(r[1]), "=r"(r[2]), "=r"(r[3]) : "r"(addr));
}

// fp16 inputs, fp32 accumulate
__device__ __forceinline__ void mma16816(float* d, const uint32_t* a,
                                         uint32_t b0, uint32_t b1) {
    asm volatile(
        "mma.sync.aligned.m16n8k16.row.col.f32.f16.f16.f32 "
        "{%0,%1,%2,%3}, {%4,%5,%6,%7}, {%8,%9}, {%0,%1,%2,%3};"
        : "+f"(d[0]), "+f"(d[1]), "+f"(d[2]), "+f"(d[3])
        : "r"(a[0]), "r"(a[1]), "r"(a[2]), "r"(a[3]), "r"(b0), "r"(b1));
}

__device__ __forceinline__ uint32_t sw128(uint32_t off) {
    return off ^ ((off >> 3) & 0x70);
}

// ============================================================================
// Prep (merged): binarize W -> fp16 AND split x into 2 fp16 planes
// ============================================================================
#define NW4   (DOUT * DIN / 4)
#define NX4   (BATCH * DIN / 4)

__global__ void prep_kernel(const float* __restrict__ W,
                            const float* __restrict__ x) {
    size_t gi = (size_t)blockIdx.x * blockDim.x + threadIdx.x;
    if (gi < (size_t)NW4) {
        float4 v = ((const float4*)W)[gi];
        float vv[4] = {v.x, v.y, v.z, v.w};
        __half s[4];
#pragma unroll
        for (int j = 0; j < 4; ++j)
            s[j] = __float2half(vv[j] > 0.f ? 1.f : (vv[j] < 0.f ? -1.f : 0.f));
        ((uint2*)g_Wb)[gi] = *(uint2*)s;
    } else {
        size_t i = gi - NW4;
        if (i >= (size_t)NX4) return;
        float4 v = ((const float4*)x)[i];
        float vv[4] = {v.x, v.y, v.z, v.w};
        __half hi[4], md[4];
#pragma unroll
        for (int j = 0; j < 4; ++j) {
            float f = vv[j];
            __half h = __float2half_rn(f);
            float r1 = f - __half2float(h);
            __half m = __float2half_rn(r1);
            hi[j] = h; md[j] = m;
        }
        ((uint2*)g_Ahi)[i] = *(uint2*)hi;
        ((uint2*)g_Amd)[i] = *(uint2*)md;
    }
}

// ============================================================================
// GEMM mainloop body — R10 structure (measured best):
//   cp_wait; top barrier; compute(kc); trailing barrier; fill(kc+3)
// ============================================================================
template <int PASS>   // 0 = hi, 1 = mid
__device__ __forceinline__ void gemm_body(float acc[4][4][4], int o0, int m0,
                                          uint32_t sbase, int tid, int wid,
                                          int lane) {
    const __half* Asrc = (PASS == 0) ? g_Ahi : g_Amd;

    auto fill = [&](int s, int kc) {
        const int kcol = kc * TK;
        const uint32_t stage = sbase + s * STAGE_BYTES;
#pragma unroll
        for (int iter = 0; iter < 8; ++iter) {
            int t = tid + iter * 256;
            int u = t & 1023;
            int row = u >> 3, c16 = u & 7;
            uint32_t loff = sw128((uint32_t)(row * KROWB + c16 * 16));
            if (t < 1024) {
                const void* src = Asrc + (size_t)(m0 + row) * DIN + kcol + c16 * 8;
                cp_async16(stage + loff, src);
            } else {
                const void* src = g_Wb + (size_t)(o0 + row) * DIN + kcol + c16 * 8;
                cp_async16(stage + TILE16K + loff, src);
            }
        }
        cp_commit();
    };

    const int lrow = lane & 15;
    const int lkh  = (lane >> 4) * 16;
    const int wm = (wid & 1) * 64;
    const int wn = (wid >> 1) * 32;
    uint32_t arow[4], brow[2];
#pragma unroll
    for (int mi = 0; mi < 4; ++mi) arow[mi] = (uint32_t)((wm + mi * 16 + lrow) * KROWB);
#pragma unroll
    for (int nt = 0; nt < 2; ++nt) brow[nt] = (uint32_t)((wn + nt * 16 + lrow) * KROWB);

    fill(0, 0); fill(1, 1); fill(2, 2);

    for (int kc = 0; kc < NCHUNK; ++kc) {
        if      (kc <= NCHUNK - 3) cp_wait<2>();
        else if (kc == NCHUNK - 2) cp_wait<1>();
        else                       cp_wait<0>();
        __syncthreads();

        const uint32_t stage = sbase + (kc % NSTAGE) * STAGE_BYTES;
        const uint32_t Bb = stage + TILE16K;
#pragma unroll
        for (int ks = 0; ks < 4; ++ks) {
            const uint32_t kb = (uint32_t)(ks * 32 + lkh);
            uint32_t bf[2][4];
#pragma unroll
            for (int nt = 0; nt < 2; ++nt) ldmx4(bf[nt], Bb + sw128(brow[nt] + kb));
            uint32_t af[4][4];
#pragma unroll
            for (int mi = 0; mi < 4; ++mi) ldmx4(af[mi], stage + sw128(arow[mi] + kb));
#pragma unroll
            for (int mi = 0; mi < 4; ++mi) {
#pragma unroll
                for (int ni = 0; ni < 4; ++ni) {
                    const int nt = ni >> 1, sel = ni & 1;
                    mma16816(acc[mi][ni], af[mi], bf[nt][sel], bf[nt][sel + 2]);
                }
            }
        }
        __syncthreads();
        if (kc + NSTAGE < NCHUNK) fill(kc % NSTAGE, kc + NSTAGE);
    }
}

// ============================================================================
// Kernel 3a: GEMM hi pass: g_y = hi . Wb^T
// ============================================================================
__global__ void __launch_bounds__(256, 2)
gemm_hi_kernel() {
    extern __shared__ __align__(1024) char smem[];
    const uint32_t sbase = smem_u32(smem);
    const int tid  = threadIdx.x;
    const int wid  = tid >> 5;
    const int lane = tid & 31;
    const int o0 = blockIdx.x * TN;
    const int m0 = blockIdx.y * TM;

    float acc[4][4][4];
#pragma unroll
    for (int a = 0; a < 4; ++a)
#pragma unroll
        for (int b = 0; b < 4; ++b)
#pragma unroll
            for (int c = 0; c < 4; ++c) acc[a][b][c] = 0.f;

    gemm_body<0>(acc, o0, m0, sbase, tid, wid, lane);

    const int wm = (wid & 1) * 64;
    const int wn = (wid >> 1) * 32;
    const int r0 = lane >> 2;
    const int c0 = (lane & 3) * 2;
#pragma unroll
    for (int mi = 0; mi < 4; ++mi) {
        const int row = m0 + wm + mi * 16 + r0;
        float* yr = g_y + (size_t)row * DOUT;
#pragma unroll
        for (int ni = 0; ni < 4; ++ni) {
            const int col = o0 + wn + ni * 8 + c0;
            float2 v0 = {acc[mi][ni][0], acc[mi][ni][1]};
            float2 v1 = {acc[mi][ni][2], acc[mi][ni][3]};
            *(float2*)(yr + col) = v0;
            *(float2*)(yr + (size_t)8 * DOUT + col) = v1;
        }
    }
}

// ============================================================================
// Kernel 3b: GEMM mid pass: y = (y_hi + mid.Wb^T) + bias, PLUS column stats
//   for this CTA's 128x128 tile (seg = blockIdx.y), via smem reduction in
//   the (then dead) stage smem. Replaces stats1.
// ============================================================================
__global__ void __launch_bounds__(256, 2)
gemm_mid_kernel(const float* __restrict__ bias) {
    extern __shared__ __align__(1024) char smem[];
    const uint32_t sbase = smem_u32(smem);
    const int tid  = threadIdx.x;
    const int wid  = tid >> 5;
    const int lane = tid & 31;
    const int o0 = blockIdx.x * TN;
    const int m0 = blockIdx.y * TM;

    float acc[4][4][4];
#pragma unroll
    for (int a = 0; a < 4; ++a)
#pragma unroll
        for (int b = 0; b < 4; ++b)
#pragma unroll
            for (int c = 0; c < 4; ++c) acc[a][b][c] = 0.f;

    gemm_body<1>(acc, o0, m0, sbase, tid, wid, lane);
    // mainloop ended with __syncthreads(): stage smem is reusable.

    const int wm = (wid & 1) * 64;
    const int wn = (wid >> 1) * 32;
    const int r0 = lane >> 2;
    const int c0 = (lane & 3) * 2;

    float csum[4][2], csq[4][2];
#pragma unroll
    for (int ni = 0; ni < 4; ++ni) {
        csum[ni][0] = csum[ni][1] = 0.f;
        csq[ni][0] = csq[ni][1] = 0.f;
    }

#pragma unroll
    for (int mi = 0; mi < 4; ++mi) {
        const int row = m0 + wm + mi * 16 + r0;
        float* yr = g_y + (size_t)row * DOUT;
#pragma unroll
        for (int ni = 0; ni < 4; ++ni) {
            const int col = o0 + wn + ni * 8 + c0;
            const float bx = bias[col], by = bias[col + 1];
            float2 h0 = *(float2*)(yr + col);
            float2 h1 = *(float2*)(yr + (size_t)8 * DOUT + col);
            float v00 = (h0.x + acc[mi][ni][0]) + bx;
            float v01 = (h0.y + acc[mi][ni][1]) + by;
            float v10 = (h1.x + acc[mi][ni][2]) + bx;
            float v11 = (h1.y + acc[mi][ni][3]) + by;
            float2 w0 = {v00, v01};
            float2 w1 = {v10, v11};
            *(float2*)(yr + col) = w0;
            *(float2*)(yr + (size_t)8 * DOUT + col) = w1;
            csum[ni][0] += v00 + v10;  csum[ni][1] += v01 + v11;
            csq[ni][0]  += v00 * v00 + v10 * v10;
            csq[ni][1]  += v01 * v01 + v11 * v11;
        }
    }

    // smem reduction: [16 rowgroups][128 cols] for sum and sumsq
    float* ssum = (float*)smem;            // 2048 floats
    float* ssq  = ssum + 16 * TN;          // 2048 floats
    const int rg = (wid & 1) * 8 + r0;     // 0..15
#pragma unroll
    for (int ni = 0; ni < 4; ++ni) {
#pragma unroll
        for (int j = 0; j < 2; ++j) {
            const int lc = wn + ni * 8 + c0 + j;   // 0..127 local col
            ssum[rg * TN + lc] = csum[ni][j];
            ssq [rg * TN + lc] = csq[ni][j];
        }
    }
    __syncthreads();

    if (tid < TN) {
        float s = 0.f;
#pragma unroll
        for (int g = 0; g < 16; ++g) s += ssum[g * TN + tid];
        g_psum[blockIdx.y * DOUT + o0 + tid] = s;
    } else {
        const int lc = tid - TN;
        float q = 0.f;
#pragma unroll
        for (int g = 0; g < 16; ++g) q += ssq[g * TN + lc];
        g_psumsq[blockIdx.y * DOUT + o0 + lc] = q;
    }
}

// ============================================================================
// Kernel 5: finalize mean / rstd — 8 threads/column, 128 blocks (all SMs),
//   8 independent segment loads per thread (MLP), fp64 smem combine.
// ============================================================================
__global__ void stats2_kernel() {
    __shared__ double sh_s[8][32];
    __shared__ double sh_q[8][32];
    const int lc   = threadIdx.x & 31;             // column within block
    const int part = threadIdx.x >> 5;             // 0..7 segment eighth
    const int col  = blockIdx.x * 32 + lc;

    double s = 0.0, q = 0.0;
#pragma unroll
    for (int g = 0; g < 8; ++g) {
        const int seg = part * 8 + g;
        s += (double)g_psum[seg * DOUT + col];
        q += (double)g_psumsq[seg * DOUT + col];
    }
    sh_s[part][lc] = s;
    sh_q[part][lc] = q;
    __syncthreads();

    if (part == 0) {
        double st = ((sh_s[0][lc] + sh_s[1][lc]) + (sh_s[2][lc] + sh_s[3][lc]))
                  + ((sh_s[4][lc] + sh_s[5][lc]) + (sh_s[6][lc] + sh_s[7][lc]));
        double qt = ((sh_q[0][lc] + sh_q[1][lc]) + (sh_q[2][lc] + sh_q[3][lc]))
                  + ((sh_q[4][lc] + sh_q[5][lc]) + (sh_q[6][lc] + sh_q[7][lc]));
        const double inv_n = 1.0 / (double)BATCH;
        double mean = st * inv_n;
        double var = qt * inv_n - mean * mean;
        if (var < 0.0) var = 0.0;
        g_mean[col] = (float)mean;
        g_rstd[col] = (float)(1.0 / sqrt(var + 1e-5));
    }
}

// ============================================================================
// Kernel 6: normalize + sign -> out   (4 elems/thread — proven form)
// ============================================================================
__global__ void sign_kernel(const float* __restrict__ gamma,
                            const float* __restrict__ beta,
                            float* __restrict__ out) {
    size_t i = (size_t)blockIdx.x * blockDim.x + threadIdx.x;
    const size_t n4 = (size_t)BATCH * DOUT / 4;
    if (i >= n4) return;
    const int o = (int)((i * 4) & (DOUT - 1));
    float4 y = ((const float4*)g_y)[i];
    float yy[4] = {y.x, y.y, y.z, y.w};
    float4 r;
    float* rr = &r.x;
#pragma unroll
    for (int j = 0; j < 4; ++j) {
        float v = (yy[j] - g_mean[o + j]) * g_rstd[o + j] * gamma[o + j] + beta[o + j];
        rr[j] = (v > 0.f) ? 1.f : ((v < 0.f) ? -1.f : 0.f);
    }
    ((float4*)out)[i] = r;
}

// ============================================================================
// Launcher
// ============================================================================
extern "C" void kernel_launch(void* const* d_in, const int* in_sizes, int n_in,
                              void* d_out, int out_size) {
    const float* x     = (const float*)d_in[0];
    const float* W     = (const float*)d_in[1];
    const float* b     = (const float*)d_in[2];
    const float* gamma = (const float*)d_in[3];
    const float* beta  = (const float*)d_in[4];
    float* out = (float*)d_out;

    cudaFuncSetAttribute(gemm_hi_kernel,
                         cudaFuncAttributeMaxDynamicSharedMemorySize, GEMM_SMEM);
    cudaFuncSetAttribute(gemm_mid_kernel,
                         cudaFuncAttributeMaxDynamicSharedMemorySize, GEMM_SMEM);

    {   // merged prep: binarize W -> fp16, split x into hi/mid fp16 planes
        const long long total = (long long)NW4 + NX4;
        prep_kernel<<<(int)((total + 255) / 256), 256>>>(W, x);
    }
    {   // GEMM hi then mid (mid also emits column stats partials)
        dim3 grid(DOUT / TN, BATCH / TM);   // (32, 64)
        gemm_hi_kernel<<<grid, 256, GEMM_SMEM>>>();
        gemm_mid_kernel<<<grid, 256, GEMM_SMEM>>>(b);
    }
    {   // finalize stats, then normalize + sign
        stats2_kernel<<<DOUT / 32, 256>>>();
        const int n4 = BATCH * DOUT / 4;
        sign_kernel<<<(n4 + 255) / 256, 256>>>(gamma, beta, out);
    }
}

// round 17
// speedup vs baseline: 3.5840x; 1.0216x over previous
#include <cuda_runtime.h>
#include <cuda_fp16.h>
#include <cstdint>

// ============================================================================
// Shapes: y = x[8192,4096] @ sign(W)[4096,4096]^T ; BN over batch; sign
// 2-plane fp16 split: x = hi + mid, residual <= 2^-23 |x| (negligible).
// R17 = R16/R14 (session best: 1529.9us) + vectorized sign param loads
//       (float4 for mean/rstd/gamma/beta; identical arithmetic).
// ============================================================================
#define BATCH   8192
#define DIN     4096
#define DOUT    4096

// CTA 128(M) x 128(N), 8 warps 2(M)x4(N), warp tile 64x32, K chunk 64
#define TM      128
#define TN      128
#define TK      64
#define KROWB   128
#define NCHUNK  (DIN / TK)                     // 64

#define TILE16K       (TM * KROWB)             // 16384 (one 128x64 fp16 tile)
#define STAGE_BYTES   (2 * TILE16K)            // 32KB: A + B
#define NSTAGE        3
#define GEMM_SMEM     (NSTAGE * STAGE_BYTES)   // 98304 -> 2 CTAs/SM

#define NSEG    64                              // = gridDim.y of GEMM

// ============================================================================
// Scratch (device globals — allocation-free rule)
// ============================================================================
__device__ __half g_Wb [(size_t)DOUT * DIN];
__device__ __half g_Ahi[(size_t)BATCH * DIN];
__device__ __half g_Amd[(size_t)BATCH * DIN];
__device__ float  g_y  [(size_t)BATCH * DOUT];
__device__ float  g_psum  [NSEG * DOUT];
__device__ float  g_psumsq[NSEG * DOUT];
__device__ __align__(16) float g_mean[DOUT];
__device__ __align__(16) float g_rstd[DOUT];

// ============================================================================
// Helpers (baseline-PTX only: cp.async / ldmatrix / mma.sync)
// ============================================================================
__device__ __forceinline__ uint32_t smem_u32(const void* p) {
    uint32_t a;
    asm("{ .reg .u64 t; cvta.to.shared.u64 t, %1; cvt.u32.u64 %0, t; }"
        : "=r"(a) : "l"(p));
    return a;
}

__device__ __forceinline__ void cp_async16(uint32_t dst, const void* src) {
    asm volatile("cp.async.cg.shared.global [%0], [%1], 16;\n"
                 :: "r"(dst), "l"(src) : "memory");
}
__device__ __forceinline__ void cp_commit() {
    asm volatile("cp.async.commit_group;\n" ::: "memory");
}
template <int N>
__device__ __forceinline__ void cp_wait() {
    asm volatile("cp.async.wait_group %0;\n" :: "n"(N) : "memory");
}

__device__ __forceinline__ void ldmx4(uint32_t* r, uint32_t addr) {
    asm volatile("ldmatrix.sync.aligned.m8n8.x4.shared.b16 {%0,%1,%2,%3}, [%4];"
                 : "=r"(r[0]), "=r"(r[1]), "=r"(r[2]), "=r"(r[3]) : "r"(addr));
}

// fp16 inputs, fp32 accumulate
__device__ __forceinline__ void mma16816(float* d, const uint32_t* a,
                                         uint32_t b0, uint32_t b1) {
    asm volatile(
        "mma.sync.aligned.m16n8k16.row.col.f32.f16.f16.f32 "
        "{%0,%1,%2,%3}, {%4,%5,%6,%7}, {%8,%9}, {%0,%1,%2,%3};"
        : "+f"(d[0]), "+f"(d[1]), "+f"(d[2]), "+f"(d[3])
        : "r"(a[0]), "r"(a[1]), "r"(a[2]), "r"(a[3]), "r"(b0), "r"(b1));
}

__device__ __forceinline__ uint32_t sw128(uint32_t off) {
    return off ^ ((off >> 3) & 0x70);
}

// ============================================================================
// Prep (merged): binarize W -> fp16 AND split x into 2 fp16 planes
// ============================================================================
#define NW4   (DOUT * DIN / 4)
#define NX4   (BATCH * DIN / 4)

__global__ void prep_kernel(const float* __restrict__ W,
                            const float* __restrict__ x) {
    size_t gi = (size_t)blockIdx.x * blockDim.x + threadIdx.x;
    if (gi < (size_t)NW4) {
        float4 v = ((const float4*)W)[gi];
        float vv[4] = {v.x, v.y, v.z, v.w};
        __half s[4];
#pragma unroll
        for (int j = 0; j < 4; ++j)
            s[j] = __float2half(vv[j] > 0.f ? 1.f : (vv[j] < 0.f ? -1.f : 0.f));
        ((uint2*)g_Wb)[gi] = *(uint2*)s;
    } else {
        size_t i = gi - NW4;
        if (i >= (size_t)NX4) return;
        float4 v = ((const float4*)x)[i];
        float vv[4] = {v.x, v.y, v.z, v.w};
        __half hi[4], md[4];
#pragma unroll
        for (int j = 0; j < 4; ++j) {
            float f = vv[j];
            __half h = __float2half_rn(f);
            float r1 = f - __half2float(h);
            __half m = __float2half_rn(r1);
            hi[j] = h; md[j] = m;
        }
        ((uint2*)g_Ahi)[i] = *(uint2*)hi;
        ((uint2*)g_Amd)[i] = *(uint2*)md;
    }
}

// ============================================================================
// GEMM mainloop body — R10 structure (measured best):
//   cp_wait; top barrier; compute(kc); trailing barrier; fill(kc+3)
// ============================================================================
template <int PASS>   // 0 = hi, 1 = mid
__device__ __forceinline__ void gemm_body(float acc[4][4][4], int o0, int m0,
                                          uint32_t sbase, int tid, int wid,
                                          int lane) {
    const __half* Asrc = (PASS == 0) ? g_Ahi : g_Amd;

    auto fill = [&](int s, int kc) {
        const int kcol = kc * TK;
        const uint32_t stage = sbase + s * STAGE_BYTES;
#pragma unroll
        for (int iter = 0; iter < 8; ++iter) {
            int t = tid + iter * 256;
            int u = t & 1023;
            int row = u >> 3, c16 = u & 7;
            uint32_t loff = sw128((uint32_t)(row * KROWB + c16 * 16));
            if (t < 1024) {
                const void* src = Asrc + (size_t)(m0 + row) * DIN + kcol + c16 * 8;
                cp_async16(stage + loff, src);
            } else {
                const void* src = g_Wb + (size_t)(o0 + row) * DIN + kcol + c16 * 8;
                cp_async16(stage + TILE16K + loff, src);
            }
        }
        cp_commit();
    };

    const int lrow = lane & 15;
    const int lkh  = (lane >> 4) * 16;
    const int wm = (wid & 1) * 64;
    const int wn = (wid >> 1) * 32;
    uint32_t arow[4], brow[2];
#pragma unroll
    for (int mi = 0; mi < 4; ++mi) arow[mi] = (uint32_t)((wm + mi * 16 + lrow) * KROWB);
#pragma unroll
    for (int nt = 0; nt < 2; ++nt) brow[nt] = (uint32_t)((wn + nt * 16 + lrow) * KROWB);

    fill(0, 0); fill(1, 1); fill(2, 2);

    for (int kc = 0; kc < NCHUNK; ++kc) {
        if      (kc <= NCHUNK - 3) cp_wait<2>();
        else if (kc == NCHUNK - 2) cp_wait<1>();
        else                       cp_wait<0>();
        __syncthreads();

        const uint32_t stage = sbase + (kc % NSTAGE) * STAGE_BYTES;
        const uint32_t Bb = stage + TILE16K;
#pragma unroll
        for (int ks = 0; ks < 4; ++ks) {
            const uint32_t kb = (uint32_t)(ks * 32 + lkh);
            uint32_t bf[2][4];
#pragma unroll
            for (int nt = 0; nt < 2; ++nt) ldmx4(bf[nt], Bb + sw128(brow[nt] + kb));
            uint32_t af[4][4];
#pragma unroll
            for (int mi = 0; mi < 4; ++mi) ldmx4(af[mi], stage + sw128(arow[mi] + kb));
#pragma unroll
            for (int mi = 0; mi < 4; ++mi) {
#pragma unroll
                for (int ni = 0; ni < 4; ++ni) {
                    const int nt = ni >> 1, sel = ni & 1;
                    mma16816(acc[mi][ni], af[mi], bf[nt][sel], bf[nt][sel + 2]);
                }
            }
        }
        __syncthreads();
        if (kc + NSTAGE < NCHUNK) fill(kc % NSTAGE, kc + NSTAGE);
    }
}

// ============================================================================
// Kernel 3a: GEMM hi pass: g_y = hi . Wb^T
// ============================================================================
__global__ void __launch_bounds__(256, 2)
gemm_hi_kernel() {
    extern __shared__ __align__(1024) char smem[];
    const uint32_t sbase = smem_u32(smem);
    const int tid  = threadIdx.x;
    const int wid  = tid >> 5;
    const int lane = tid & 31;
    const int o0 = blockIdx.x * TN;
    const int m0 = blockIdx.y * TM;

    float acc[4][4][4];
#pragma unroll
    for (int a = 0; a < 4; ++a)
#pragma unroll
        for (int b = 0; b < 4; ++b)
#pragma unroll
            for (int c = 0; c < 4; ++c) acc[a][b][c] = 0.f;

    gemm_body<0>(acc, o0, m0, sbase, tid, wid, lane);

    const int wm = (wid & 1) * 64;
    const int wn = (wid >> 1) * 32;
    const int r0 = lane >> 2;
    const int c0 = (lane & 3) * 2;
#pragma unroll
    for (int mi = 0; mi < 4; ++mi) {
        const int row = m0 + wm + mi * 16 + r0;
        float* yr = g_y + (size_t)row * DOUT;
#pragma unroll
        for (int ni = 0; ni < 4; ++ni) {
            const int col = o0 + wn + ni * 8 + c0;
            float2 v0 = {acc[mi][ni][0], acc[mi][ni][1]};
            float2 v1 = {acc[mi][ni][2], acc[mi][ni][3]};
            *(float2*)(yr + col) = v0;
            *(float2*)(yr + (size_t)8 * DOUT + col) = v1;
        }
    }
}

// ============================================================================
// Kernel 3b: GEMM mid pass: y = (y_hi + mid.Wb^T) + bias, PLUS column stats
//   for this CTA's 128x128 tile (seg = blockIdx.y), via smem reduction in
//   the (then dead) stage smem. Replaces stats1.
// ============================================================================
__global__ void __launch_bounds__(256, 2)
gemm_mid_kernel(const float* __restrict__ bias) {
    extern __shared__ __align__(1024) char smem[];
    const uint32_t sbase = smem_u32(smem);
    const int tid  = threadIdx.x;
    const int wid  = tid >> 5;
    const int lane = tid & 31;
    const int o0 = blockIdx.x * TN;
    const int m0 = blockIdx.y * TM;

    float acc[4][4][4];
#pragma unroll
    for (int a = 0; a < 4; ++a)
#pragma unroll
        for (int b = 0; b < 4; ++b)
#pragma unroll
            for (int c = 0; c < 4; ++c) acc[a][b][c] = 0.f;

    gemm_body<1>(acc, o0, m0, sbase, tid, wid, lane);
    // mainloop ended with __syncthreads(): stage smem is reusable.

    const int wm = (wid & 1) * 64;
    const int wn = (wid >> 1) * 32;
    const int r0 = lane >> 2;
    const int c0 = (lane & 3) * 2;

    float csum[4][2], csq[4][2];
#pragma unroll
    for (int ni = 0; ni < 4; ++ni) {
        csum[ni][0] = csum[ni][1] = 0.f;
        csq[ni][0] = csq[ni][1] = 0.f;
    }

#pragma unroll
    for (int mi = 0; mi < 4; ++mi) {
        const int row = m0 + wm + mi * 16 + r0;
        float* yr = g_y + (size_t)row * DOUT;
#pragma unroll
        for (int ni = 0; ni < 4; ++ni) {
            const int col = o0 + wn + ni * 8 + c0;
            const float bx = bias[col], by = bias[col + 1];
            float2 h0 = *(float2*)(yr + col);
            float2 h1 = *(float2*)(yr + (size_t)8 * DOUT + col);
            float v00 = (h0.x + acc[mi][ni][0]) + bx;
            float v01 = (h0.y + acc[mi][ni][1]) + by;
            float v10 = (h1.x + acc[mi][ni][2]) + bx;
            float v11 = (h1.y + acc[mi][ni][3]) + by;
            float2 w0 = {v00, v01};
            float2 w1 = {v10, v11};
            *(float2*)(yr + col) = w0;
            *(float2*)(yr + (size_t)8 * DOUT + col) = w1;
            csum[ni][0] += v00 + v10;  csum[ni][1] += v01 + v11;
            csq[ni][0]  += v00 * v00 + v10 * v10;
            csq[ni][1]  += v01 * v01 + v11 * v11;
        }
    }

    // smem reduction: [16 rowgroups][128 cols] for sum and sumsq
    float* ssum = (float*)smem;            // 2048 floats
    float* ssq  = ssum + 16 * TN;          // 2048 floats
    const int rg = (wid & 1) * 8 + r0;     // 0..15
#pragma unroll
    for (int ni = 0; ni < 4; ++ni) {
#pragma unroll
        for (int j = 0; j < 2; ++j) {
            const int lc = wn + ni * 8 + c0 + j;   // 0..127 local col
            ssum[rg * TN + lc] = csum[ni][j];
            ssq [rg * TN + lc] = csq[ni][j];
        }
    }
    __syncthreads();

    if (tid < TN) {
        float s = 0.f;
#pragma unroll
        for (int g = 0; g < 16; ++g) s += ssum[g * TN + tid];
        g_psum[blockIdx.y * DOUT + o0 + tid] = s;
    } else {
        const int lc = tid - TN;
        float q = 0.f;
#pragma unroll
        for (int g = 0; g < 16; ++g) q += ssq[g * TN + lc];
        g_psumsq[blockIdx.y * DOUT + o0 + lc] = q;
    }
}

// ============================================================================
// Kernel 5: finalize mean / rstd — 8 threads/column, 128 blocks (all SMs),
//   8 independent segment loads per thread (MLP), fp64 smem combine.
// ============================================================================
__global__ void stats2_kernel() {
    __shared__ double sh_s[8][32];
    __shared__ double sh_q[8][32];
    const int lc   = threadIdx.x & 31;             // column within block
    const int part = threadIdx.x >> 5;             // 0..7 segment eighth
    const int col  = blockIdx.x * 32 + lc;

    double s = 0.0, q = 0.0;
#pragma unroll
    for (int g = 0; g < 8; ++g) {
        const int seg = part * 8 + g;
        s += (double)g_psum[seg * DOUT + col];
        q += (double)g_psumsq[seg * DOUT + col];
    }
    sh_s[part][lc] = s;
    sh_q[part][lc] = q;
    __syncthreads();

    if (part == 0) {
        double st = ((sh_s[0][lc] + sh_s[1][lc]) + (sh_s[2][lc] + sh_s[3][lc]))
                  + ((sh_s[4][lc] + sh_s[5][lc]) + (sh_s[6][lc] + sh_s[7][lc]));
        double qt = ((sh_q[0][lc] + sh_q[1][lc]) + (sh_q[2][lc] + sh_q[3][lc]))
                  + ((sh_q[4][lc] + sh_q[5][lc]) + (sh_q[6][lc] + sh_q[7][lc]));
        const double inv_n = 1.0 / (double)BATCH;
        double mean = st * inv_n;
        double var = qt * inv_n - mean * mean;
        if (var < 0.0) var = 0.0;
        g_mean[col] = (float)mean;
        g_rstd[col] = (float)(1.0 / sqrt(var + 1e-5));
    }
}

// ============================================================================
// Kernel 6: normalize + sign -> out
//   4 elems/thread; mean/rstd/gamma/beta loaded as float4 (o % 4 == 0).
//   Arithmetic identical to the scalar-load version.
// ============================================================================
__global__ void sign_kernel(const float* __restrict__ gamma,
                            const float* __restrict__ beta,
                            float* __restrict__ out) {
    size_t i = (size_t)blockIdx.x * blockDim.x + threadIdx.x;
    const size_t n4 = (size_t)BATCH * DOUT / 4;
    if (i >= n4) return;
    const int o4 = (int)(i & (DOUT / 4 - 1));     // float4 index within row
    float4 y = ((const float4*)g_y)[i];
    float4 mn = ((const float4*)g_mean)[o4];
    float4 rs = ((const float4*)g_rstd)[o4];
    float4 gm = ((const float4*)gamma)[o4];
    float4 bt = ((const float4*)beta)[o4];
    float yy[4] = {y.x, y.y, y.z, y.w};
    float mm[4] = {mn.x, mn.y, mn.z, mn.w};
    float rr_[4] = {rs.x, rs.y, rs.z, rs.w};
    float gg[4] = {gm.x, gm.y, gm.z, gm.w};
    float bb[4] = {bt.x, bt.y, bt.z, bt.w};
    float4 r;
    float* rr = &r.x;
#pragma unroll
    for (int j = 0; j < 4; ++j) {
        float v = (yy[j] - mm[j]) * rr_[j] * gg[j] + bb[j];
        rr[j] = (v > 0.f) ? 1.f : ((v < 0.f) ? -1.f : 0.f);
    }
    ((float4*)out)[i] = r;
}

// ============================================================================
// Launcher
// ============================================================================
extern "C" void kernel_launch(void* const* d_in, const int* in_sizes, int n_in,
                              void* d_out, int out_size) {
    const float* x     = (const float*)d_in[0];
    const float* W     = (const float*)d_in[1];
    const float* b     = (const float*)d_in[2];
    const float* gamma = (const float*)d_in[3];
    const float* beta  = (const float*)d_in[4];
    float* out = (float*)d_out;

    cudaFuncSetAttribute(gemm_hi_kernel,
                         cudaFuncAttributeMaxDynamicSharedMemorySize, GEMM_SMEM);
    cudaFuncSetAttribute(gemm_mid_kernel,
                         cudaFuncAttributeMaxDynamicSharedMemorySize, GEMM_SMEM);

    {   // merged prep: binarize W -> fp16, split x into hi/mid fp16 planes
        const long long total = (long long)NW4 + NX4;
        prep_kernel<<<(int)((total + 255) / 256), 256>>>(W, x);
    }
    {   // GEMM hi then mid (mid also emits column stats partials)
        dim3 grid(DOUT / TN, BATCH / TM);   // (32, 64)
        gemm_hi_kernel<<<grid, 256, GEMM_SMEM>>>();
        gemm_mid_kernel<<<grid, 256, GEMM_SMEM>>>(b);
    }
    {   // finalize stats, then normalize + sign
        stats2_kernel<<<DOUT / 32, 256>>>();
        const int n4 = BATCH * DOUT / 4;
        sign_kernel<<<(n4 + 255) / 256, 256>>>(gamma, beta, out);
    }
}